// round 10
// baseline (speedup 1.0000x reference)
#include <cuda_runtime.h>
#include <cstdint>
#include <math.h>

#define Bb 2
#define Ss 2048
#define Hh 1024
#define NHh 16
#define Dd 64
#define MROWS (Bb * Ss)   // 4096

typedef unsigned long long ull;

// Scratch (no cudaMalloc allowed): Q, K, V, ctx each [4096, 1024] fp32 = 16 MiB
__device__ float g_q[MROWS * Hh];
__device__ float g_k[MROWS * Hh];
__device__ float g_v[MROWS * Hh];
__device__ float g_ctx[MROWS * Hh];

// ===========================================================================
// f32x2 packed-math helpers
// ===========================================================================
__device__ __forceinline__ ull pk2(float x, float y) {
    ull r;
    asm("mov.b64 %0, {%1, %2};" : "=l"(r) : "f"(x), "f"(y));
    return r;
}
__device__ __forceinline__ void upk2(ull v, float& x, float& y) {
    asm("mov.b64 {%0, %1}, %2;" : "=f"(x), "=f"(y) : "l"(v));
}
__device__ __forceinline__ ull ffma2(ull a, ull b, ull c) {
    ull d;
    asm("fma.rn.f32x2 %0, %1, %2, %3;" : "=l"(d) : "l"(a), "l"(b), "l"(c));
    return d;
}
__device__ __forceinline__ ull fmul2(ull a, ull b) {
    ull d;
    asm("mul.rn.f32x2 %0, %1, %2;" : "=l"(d) : "l"(a), "l"(b));
    return d;
}

// ===========================================================================
// GEMM core (NT, FFMA2, double-buffered, A stored pre-duplicated as (a,a)
// pairs in smem so the inner loop has zero packing MOVs):
// C[m][n] = sum_k A[m][k]*W[n][k] + bias[n].  M=4096, N=1024, K=1024.
// Block 128x128, K-tile 16, 256 thr, 8x8/thread.
// ===========================================================================
__device__ __forceinline__ void gemm_core(
    const float* __restrict__ A, const float* __restrict__ W,
    const float* __restrict__ bias, float* __restrict__ C,
    ull (*As)[16][132], float (*Bs)[16][132])
{
    const int K = 1024, N = 1024;
    const int tid = threadIdx.x;
    const int tx = tid % 16;          // n direction
    const int ty = tid / 16;          // m direction
    const int m0 = blockIdx.y * 128;
    const int n0 = blockIdx.x * 128;
    const int lr = tid / 4;           // 0..63
    const int lc = (tid % 4) * 4;     // 0,4,8,12

    ull acc2[8][4];
#pragma unroll
    for (int i = 0; i < 8; i++)
#pragma unroll
        for (int j = 0; j < 4; j++) acc2[i][j] = 0ULL;

    const float* Arow0 = A + (size_t)(m0 + lr) * K + lc;
    const float* Arow1 = A + (size_t)(m0 + lr + 64) * K + lc;
    const float* Brow0 = W + (size_t)(n0 + lr) * K + lc;
    const float* Brow1 = W + (size_t)(n0 + lr + 64) * K + lc;

    // prefetch + store tile 0
    {
        float4 a0 = *(const float4*)Arow0;
        float4 a1 = *(const float4*)Arow1;
        float4 b0 = *(const float4*)Brow0;
        float4 b1 = *(const float4*)Brow1;
        As[0][lc + 0][lr] = pk2(a0.x, a0.x); As[0][lc + 1][lr] = pk2(a0.y, a0.y);
        As[0][lc + 2][lr] = pk2(a0.z, a0.z); As[0][lc + 3][lr] = pk2(a0.w, a0.w);
        As[0][lc + 0][lr + 64] = pk2(a1.x, a1.x);
        As[0][lc + 1][lr + 64] = pk2(a1.y, a1.y);
        As[0][lc + 2][lr + 64] = pk2(a1.z, a1.z);
        As[0][lc + 3][lr + 64] = pk2(a1.w, a1.w);
        Bs[0][lc + 0][lr] = b0.x; Bs[0][lc + 1][lr] = b0.y;
        Bs[0][lc + 2][lr] = b0.z; Bs[0][lc + 3][lr] = b0.w;
        Bs[0][lc + 0][lr + 64] = b1.x; Bs[0][lc + 1][lr + 64] = b1.y;
        Bs[0][lc + 2][lr + 64] = b1.z; Bs[0][lc + 3][lr + 64] = b1.w;
    }
    __syncthreads();

    for (int t = 0; t < 64; t++) {
        const int cur = t & 1;
        float4 na0, na1, nb0, nb1;
        if (t < 63) {
            int k1 = (t + 1) * 16;
            na0 = *(const float4*)&Arow0[k1];
            na1 = *(const float4*)&Arow1[k1];
            nb0 = *(const float4*)&Brow0[k1];
            nb1 = *(const float4*)&Brow1[k1];
        }

#pragma unroll
        for (int kk = 0; kk < 16; kk++) {
            const ull* ap = &As[cur][kk][ty * 8];
            ulonglong2 t0 = *(const ulonglong2*)(ap + 0);
            ulonglong2 t1 = *(const ulonglong2*)(ap + 2);
            ulonglong2 t2 = *(const ulonglong2*)(ap + 4);
            ulonglong2 t3 = *(const ulonglong2*)(ap + 6);
            ull ra2[8] = {t0.x, t0.y, t1.x, t1.y, t2.x, t2.y, t3.x, t3.y};
            ull rb2[4];
#pragma unroll
            for (int j = 0; j < 4; j++)
                rb2[j] = *(const ull*)&Bs[cur][kk][2 * tx + 32 * j];
#pragma unroll
            for (int i = 0; i < 8; i++)
#pragma unroll
                for (int j = 0; j < 4; j++)
                    acc2[i][j] = ffma2(ra2[i], rb2[j], acc2[i][j]);
        }

        if (t < 63) {
            const int nb = cur ^ 1;
            As[nb][lc + 0][lr] = pk2(na0.x, na0.x);
            As[nb][lc + 1][lr] = pk2(na0.y, na0.y);
            As[nb][lc + 2][lr] = pk2(na0.z, na0.z);
            As[nb][lc + 3][lr] = pk2(na0.w, na0.w);
            As[nb][lc + 0][lr + 64] = pk2(na1.x, na1.x);
            As[nb][lc + 1][lr + 64] = pk2(na1.y, na1.y);
            As[nb][lc + 2][lr + 64] = pk2(na1.z, na1.z);
            As[nb][lc + 3][lr + 64] = pk2(na1.w, na1.w);
            Bs[nb][lc + 0][lr] = nb0.x; Bs[nb][lc + 1][lr] = nb0.y;
            Bs[nb][lc + 2][lr] = nb0.z; Bs[nb][lc + 3][lr] = nb0.w;
            Bs[nb][lc + 0][lr + 64] = nb1.x; Bs[nb][lc + 1][lr + 64] = nb1.y;
            Bs[nb][lc + 2][lr + 64] = nb1.z; Bs[nb][lc + 3][lr + 64] = nb1.w;
            __syncthreads();
        }
    }

#pragma unroll
    for (int i = 0; i < 8; i++) {
        int row = m0 + ty * 8 + i;
#pragma unroll
        for (int j = 0; j < 4; j++) {
            int col = n0 + 2 * tx + 32 * j;
            float2 bb = *(const float2*)&bias[col];
            float x, y;
            upk2(acc2[i][j], x, y);
            float2 c;
            c.x = x + bb.x;
            c.y = y + bb.y;
            *(float2*)&C[(size_t)row * N + col] = c;
        }
    }
}

// Fused QKV projection: grid.z selects {Q,K,V}
__global__ void __launch_bounds__(256) qkv_f2(
    const float* __restrict__ x,
    const float* __restrict__ wq, const float* __restrict__ bq,
    const float* __restrict__ wk, const float* __restrict__ bk,
    const float* __restrict__ wv, const float* __restrict__ bv)
{
    __shared__ __align__(16) ull As[2][16][132];
    __shared__ float Bs[2][16][132];
    const float* W; const float* bias; float* C;
    if (blockIdx.z == 0)      { W = wq; bias = bq; C = g_q; }
    else if (blockIdx.z == 1) { W = wk; bias = bk; C = g_k; }
    else                      { W = wv; bias = bv; C = g_v; }
    gemm_core(x, W, bias, C, As, Bs);
}

__global__ void __launch_bounds__(256) oproj_f2(
    const float* __restrict__ wo, const float* __restrict__ bo,
    float* __restrict__ out)
{
    __shared__ __align__(16) ull As[2][16][132];
    __shared__ float Bs[2][16][132];
    gemm_core(g_ctx, wo, bo, out, As, Bs);
}

// ===========================================================================
// Flash attention: Br=64, Bc=64, D=64, 256 threads, TARGET 3 CTAs/SM.
// tm=tid/8 (0..31), tn=tid%8. Rows {tm+32i}, i<2. QK cols {tn+8c}, c<8.
// P stays in registers; PV gets p via __shfl_sync from lane (lane&24)|(k&7),
// register index k>>3 (compile-time after unroll). No P smem, 2 syncs/tile.
// ===========================================================================
#define QPR 65
#define KPR 65
#define VR  68
#define OFF_QP 0
#define OFF_KP (32 * QPR * 8)                  // 16640
#define OFF_V  (OFF_KP + 32 * KPR * 8)         // 33280
#define SMEM_ATTN (OFF_V + 64 * VR * 4)        // 50688

__global__ void __launch_bounds__(256, 3) attn_f2()
{
    extern __shared__ char smem_raw[];
    ull*   sQp = (ull*)(smem_raw + OFF_QP);    // [dp*QPR + row], dp=0..31
    ull*   sKp = (ull*)(smem_raw + OFF_KP);    // [dp*KPR + col]
    float* sV  = (float*)(smem_raw + OFF_V);   // [k*VR + d]

    const int bh = blockIdx.y;           // 0..31
    const int b  = bh / NHh;
    const int h  = bh % NHh;
    const int q0 = blockIdx.x * 64;

    const int tid  = threadIdx.x;
    const int lane = tid & 31;
    const int tm   = tid >> 3;           // 0..31
    const int tn   = tid & 7;            // 0..7

    const float* Qb = g_q + (size_t)(b * Ss) * Hh + h * Dd;
    const float* Kb = g_k + (size_t)(b * Ss) * Hh + h * Dd;
    const float* Vb = g_v + (size_t)(b * Ss) * Hh + h * Dd;

    // Load Q tile (64 rows x 64 d) into d-pair layout
    for (int idx = tid; idx < 64 * 16; idx += 256) {
        int r = idx >> 4, f4 = idx & 15;
        float4 v = *(const float4*)&Qb[(size_t)(q0 + r) * Hh + f4 * 4];
        sQp[(2 * f4 + 0) * QPR + r] = *(ull*)&v.x;
        sQp[(2 * f4 + 1) * QPR + r] = *(ull*)&v.z;
    }

    float m[2], l[2];
    ull o2[2][4];
#pragma unroll
    for (int i = 0; i < 2; i++) {
        m[i] = -1e30f; l[i] = 0.f;
#pragma unroll
        for (int c = 0; c < 4; c++) o2[i][c] = 0ULL;
    }

    for (int kt = 0; kt < Ss; kt += 64) {
        __syncthreads();   // prev PV done reading sKp/sV
        for (int idx = tid; idx < 64 * 16; idx += 256) {
            int r = idx >> 4, f4 = idx & 15;
            float4 kv = *(const float4*)&Kb[(size_t)(kt + r) * Hh + f4 * 4];
            sKp[(2 * f4 + 0) * KPR + r] = *(ull*)&kv.x;
            sKp[(2 * f4 + 1) * KPR + r] = *(ull*)&kv.z;
            float4 vv = *(const float4*)&Vb[(size_t)(kt + r) * Hh + f4 * 4];
            *(float4*)&sV[r * VR + f4 * 4] = vv;
        }
        __syncthreads();

        // ---- S = Q K^T  (2 rows x 8 cols per thread) ----
        ull s2[2][8];
#pragma unroll
        for (int i = 0; i < 2; i++)
#pragma unroll
            for (int c = 0; c < 8; c++) s2[i][c] = 0ULL;

#pragma unroll 4
        for (int dp = 0; dp < 32; dp++) {
            ull q2[2], k2[8];
#pragma unroll
            for (int i = 0; i < 2; i++)
                q2[i] = sQp[dp * QPR + tm + 32 * i];
#pragma unroll
            for (int c = 0; c < 8; c++)
                k2[c] = sKp[dp * KPR + tn + 8 * c];
#pragma unroll
            for (int i = 0; i < 2; i++)
#pragma unroll
                for (int c = 0; c < 8; c++)
                    s2[i][c] = ffma2(q2[i], k2[c], s2[i][c]);
        }

        // ---- online softmax: P kept in registers ----
        float p[2][8];
#pragma unroll
        for (int i = 0; i < 2; i++) {
            float s[8];
            float mrow = -1e30f;
#pragma unroll
            for (int c = 0; c < 8; c++) {
                float lo, hi;
                upk2(s2[i][c], lo, hi);
                s[c] = (lo + hi) * 0.125f;     // 1/sqrt(64)
                mrow = fmaxf(mrow, s[c]);
            }
            mrow = fmaxf(mrow, __shfl_xor_sync(0xffffffffu, mrow, 1));
            mrow = fmaxf(mrow, __shfl_xor_sync(0xffffffffu, mrow, 2));
            mrow = fmaxf(mrow, __shfl_xor_sync(0xffffffffu, mrow, 4));

            float mnew  = fmaxf(m[i], mrow);
            float alpha = __expf(m[i] - mnew);
            float lsum = 0.f;
#pragma unroll
            for (int c = 0; c < 8; c++) {
                p[i][c] = __expf(s[c] - mnew);
                lsum += p[i][c];
            }
            lsum += __shfl_xor_sync(0xffffffffu, lsum, 1);
            lsum += __shfl_xor_sync(0xffffffffu, lsum, 2);
            lsum += __shfl_xor_sync(0xffffffffu, lsum, 4);
            l[i] = l[i] * alpha + lsum;
            m[i] = mnew;
            ull a2 = pk2(alpha, alpha);
#pragma unroll
            for (int c = 0; c < 4; c++) o2[i][c] = fmul2(o2[i][c], a2);
        }

        // ---- O += P V  (p via shfl, no smem P, no extra sync) ----
#pragma unroll
        for (int c8 = 0; c8 < 8; c8++) {
#pragma unroll
            for (int j = 0; j < 8; j++) {
                const int k = c8 * 8 + j;
                ull v2[4];
#pragma unroll
                for (int c = 0; c < 4; c++)
                    v2[c] = *(const ull*)&sV[k * VR + 2 * tn + 16 * c];
                const int src = (lane & 24) | j;
                float p0 = __shfl_sync(0xffffffffu, p[0][c8], src);
                float p1 = __shfl_sync(0xffffffffu, p[1][c8], src);
                ull pp0 = pk2(p0, p0);
                ull pp1 = pk2(p1, p1);
#pragma unroll
                for (int c = 0; c < 4; c++) {
                    o2[0][c] = ffma2(pp0, v2[c], o2[0][c]);
                    o2[1][c] = ffma2(pp1, v2[c], o2[1][c]);
                }
            }
        }
    }

    // Epilogue: normalize and write to concat layout [B*S, H]
#pragma unroll
    for (int i = 0; i < 2; i++) {
        const float inv = 1.f / l[i];
        const int row = q0 + tm + 32 * i;
        float* op = g_ctx + (size_t)(b * Ss + row) * Hh + h * Dd;
#pragma unroll
        for (int c = 0; c < 4; c++) {
            float x, y;
            upk2(o2[i][c], x, y);
            float2 w;
            w.x = x * inv; w.y = y * inv;
            *(float2*)&op[2 * tn + 16 * c] = w;
        }
    }
}

// ---------------------------------------------------------------------------
extern "C" void kernel_launch(void* const* d_in, const int* in_sizes, int n_in,
                              void* d_out, int out_size)
{
    const float* x  = (const float*)d_in[0];
    const float* wq = (const float*)d_in[1];
    const float* bq = (const float*)d_in[2];
    const float* wk = (const float*)d_in[3];
    const float* bk = (const float*)d_in[4];
    const float* wv = (const float*)d_in[5];
    const float* bv = (const float*)d_in[6];
    const float* wo = (const float*)d_in[7];
    const float* bo = (const float*)d_in[8];
    float* out = (float*)d_out;

    cudaFuncSetAttribute(attn_f2, cudaFuncAttributeMaxDynamicSharedMemorySize,
                         SMEM_ATTN);

    dim3 gq(1024 / 128, MROWS / 128, 3);   // (8, 32, 3)
    qkv_f2<<<gq, 256>>>(x, wq, bq, wk, bk, wv, bv);

    dim3 ga(Ss / 64, Bb * NHh);            // (32, 32)
    attn_f2<<<ga, 256, SMEM_ATTN>>>();

    dim3 gg(1024 / 128, MROWS / 128);      // (8, 32)
    oproj_f2<<<gg, 256>>>(wo, bo, out);
}

// round 12
// speedup vs baseline: 1.0645x; 1.0645x over previous
#include <cuda_runtime.h>
#include <cstdint>
#include <math.h>

#define Bb 2
#define Ss 2048
#define Hh 1024
#define NHh 16
#define Dd 64
#define MROWS (Bb * Ss)   // 4096

typedef unsigned long long ull;

// Scratch (no cudaMalloc allowed): Q, K, V, ctx each [4096, 1024] fp32 = 16 MiB
__device__ float g_q[MROWS * Hh];
__device__ float g_k[MROWS * Hh];
__device__ float g_v[MROWS * Hh];
__device__ float g_ctx[MROWS * Hh];

// ===========================================================================
// f32x2 packed-math helpers
// ===========================================================================
__device__ __forceinline__ ull pk2(float x, float y) {
    ull r;
    asm("mov.b64 %0, {%1, %2};" : "=l"(r) : "f"(x), "f"(y));
    return r;
}
__device__ __forceinline__ void upk2(ull v, float& x, float& y) {
    asm("mov.b64 {%0, %1}, %2;" : "=f"(x), "=f"(y) : "l"(v));
}
__device__ __forceinline__ ull ffma2(ull a, ull b, ull c) {
    ull d;
    asm("fma.rn.f32x2 %0, %1, %2, %3;" : "=l"(d) : "l"(a), "l"(b), "l"(c));
    return d;
}
__device__ __forceinline__ ull fmul2(ull a, ull b) {
    ull d;
    asm("mul.rn.f32x2 %0, %1, %2;" : "=l"(d) : "l"(a), "l"(b));
    return d;
}

// ===========================================================================
// GEMM core — EXACT R8 version (regs=128 -> 2 CTAs/SM, fma=66.9%).
// C[m][n] = sum_k A[m][k]*W[n][k] + bias[n].  M=4096, N=1024, K=1024.
// Block 128x128, K-tile 16, 256 thr, 8x8/thread, double-buffered smem.
// ===========================================================================
__device__ __forceinline__ void gemm_core(
    const float* __restrict__ A, const float* __restrict__ W,
    const float* __restrict__ bias, float* __restrict__ C,
    float (*As)[16][132], float (*Bs)[16][132])
{
    const int K = 1024, N = 1024;
    const int tid = threadIdx.x;
    const int tx = tid % 16;          // n direction
    const int ty = tid / 16;          // m direction
    const int m0 = blockIdx.y * 128;
    const int n0 = blockIdx.x * 128;
    const int lr = tid / 4;           // 0..63
    const int lc = (tid % 4) * 4;     // 0,4,8,12

    ull acc2[8][4];
#pragma unroll
    for (int i = 0; i < 8; i++)
#pragma unroll
        for (int j = 0; j < 4; j++) acc2[i][j] = 0ULL;

    const float* Arow0 = A + (size_t)(m0 + lr) * K + lc;
    const float* Arow1 = A + (size_t)(m0 + lr + 64) * K + lc;
    const float* Brow0 = W + (size_t)(n0 + lr) * K + lc;
    const float* Brow1 = W + (size_t)(n0 + lr + 64) * K + lc;

    // prefetch + store tile 0
    {
        float4 a0 = *(const float4*)Arow0;
        float4 a1 = *(const float4*)Arow1;
        float4 b0 = *(const float4*)Brow0;
        float4 b1 = *(const float4*)Brow1;
        As[0][lc + 0][lr] = a0.x; As[0][lc + 1][lr] = a0.y;
        As[0][lc + 2][lr] = a0.z; As[0][lc + 3][lr] = a0.w;
        As[0][lc + 0][lr + 64] = a1.x; As[0][lc + 1][lr + 64] = a1.y;
        As[0][lc + 2][lr + 64] = a1.z; As[0][lc + 3][lr + 64] = a1.w;
        Bs[0][lc + 0][lr] = b0.x; Bs[0][lc + 1][lr] = b0.y;
        Bs[0][lc + 2][lr] = b0.z; Bs[0][lc + 3][lr] = b0.w;
        Bs[0][lc + 0][lr + 64] = b1.x; Bs[0][lc + 1][lr + 64] = b1.y;
        Bs[0][lc + 2][lr + 64] = b1.z; Bs[0][lc + 3][lr + 64] = b1.w;
    }
    __syncthreads();

    for (int t = 0; t < 64; t++) {
        const int cur = t & 1;
        float4 na0, na1, nb0, nb1;
        if (t < 63) {
            int k1 = (t + 1) * 16;
            na0 = *(const float4*)&Arow0[k1];
            na1 = *(const float4*)&Arow1[k1];
            nb0 = *(const float4*)&Brow0[k1];
            nb1 = *(const float4*)&Brow1[k1];
        }

#pragma unroll
        for (int kk = 0; kk < 16; kk++) {
            float4 a0 = *(const float4*)&As[cur][kk][ty * 8];
            float4 a1 = *(const float4*)&As[cur][kk][ty * 8 + 4];
            ull ra2[8];
            ra2[0] = pk2(a0.x, a0.x); ra2[1] = pk2(a0.y, a0.y);
            ra2[2] = pk2(a0.z, a0.z); ra2[3] = pk2(a0.w, a0.w);
            ra2[4] = pk2(a1.x, a1.x); ra2[5] = pk2(a1.y, a1.y);
            ra2[6] = pk2(a1.z, a1.z); ra2[7] = pk2(a1.w, a1.w);
            ull rb2[4];
#pragma unroll
            for (int j = 0; j < 4; j++)
                rb2[j] = *(const ull*)&Bs[cur][kk][2 * tx + 32 * j];
#pragma unroll
            for (int i = 0; i < 8; i++)
#pragma unroll
                for (int j = 0; j < 4; j++)
                    acc2[i][j] = ffma2(ra2[i], rb2[j], acc2[i][j]);
        }

        if (t < 63) {
            const int nb = cur ^ 1;
            As[nb][lc + 0][lr] = na0.x; As[nb][lc + 1][lr] = na0.y;
            As[nb][lc + 2][lr] = na0.z; As[nb][lc + 3][lr] = na0.w;
            As[nb][lc + 0][lr + 64] = na1.x; As[nb][lc + 1][lr + 64] = na1.y;
            As[nb][lc + 2][lr + 64] = na1.z; As[nb][lc + 3][lr + 64] = na1.w;
            Bs[nb][lc + 0][lr] = nb0.x; Bs[nb][lc + 1][lr] = nb0.y;
            Bs[nb][lc + 2][lr] = nb0.z; Bs[nb][lc + 3][lr] = nb0.w;
            Bs[nb][lc + 0][lr + 64] = nb1.x; Bs[nb][lc + 1][lr + 64] = nb1.y;
            Bs[nb][lc + 2][lr + 64] = nb1.z; Bs[nb][lc + 3][lr + 64] = nb1.w;
            __syncthreads();
        }
    }

#pragma unroll
    for (int i = 0; i < 8; i++) {
        int row = m0 + ty * 8 + i;
#pragma unroll
        for (int j = 0; j < 4; j++) {
            int col = n0 + 2 * tx + 32 * j;
            float2 bb = *(const float2*)&bias[col];
            float x, y;
            upk2(acc2[i][j], x, y);
            float2 c;
            c.x = x + bb.x;
            c.y = y + bb.y;
            *(float2*)&C[(size_t)row * N + col] = c;
        }
    }
}

// Fused QKV projection: grid.z selects {Q,K,V}
__global__ void __launch_bounds__(256, 2) qkv_f2(
    const float* __restrict__ x,
    const float* __restrict__ wq, const float* __restrict__ bq,
    const float* __restrict__ wk, const float* __restrict__ bk,
    const float* __restrict__ wv, const float* __restrict__ bv)
{
    __shared__ float As[2][16][132];
    __shared__ float Bs[2][16][132];
    const float* W; const float* bias; float* C;
    if (blockIdx.z == 0)      { W = wq; bias = bq; C = g_q; }
    else if (blockIdx.z == 1) { W = wk; bias = bk; C = g_k; }
    else                      { W = wv; bias = bv; C = g_v; }
    gemm_core(x, W, bias, C, As, Bs);
}

__global__ void __launch_bounds__(256, 2) oproj_f2(
    const float* __restrict__ wo, const float* __restrict__ bo,
    float* __restrict__ out)
{
    __shared__ float As[2][16][132];
    __shared__ float Bs[2][16][132];
    gemm_core(g_ctx, wo, bo, out, As, Bs);
}

// ===========================================================================
// Flash attention: Br=128, Bc=64, D=64, 512 threads, 1 CTA/SM,
// DOUBLE-BUFFERED K/V tiles -> 2 syncs/tile + LDG prefetch into registers.
// tm=tid/8 (0..63), tn=tid%8. Rows {tm+64i}, i<2. QK cols {tn+8c}, c<8.
// PV d-pairs {2tn+16c}. All hot LDS are broadcasts / conflict-free.
// ===========================================================================
#define QPR 129
#define KPR 65
#define VR  68
#define PR  72
#define KTILE (32 * KPR)                       // ull per K buffer
#define VTILE (64 * VR)                        // float per V buffer
#define OFF_Q  0
#define OFF_K  (32 * QPR * 8)                  // 33024
#define OFF_V  (OFF_K + 2 * KTILE * 8)         // 66304
#define OFF_P  (OFF_V + 2 * VTILE * 4)         // 101120
#define SMEM_ATTN (OFF_P + 128 * PR * 4)       // 137984

__global__ void __launch_bounds__(512, 1) attn_f2()
{
    extern __shared__ char smem_raw[];
    ull*   sQp = (ull*)(smem_raw + OFF_Q);     // [dp*QPR + row], dp=0..31
    ull*   sKp = (ull*)(smem_raw + OFF_K);     // 2 buffers of [dp*KPR + col]
    float* sV  = (float*)(smem_raw + OFF_V);   // 2 buffers of [k*VR + d]
    float* sP  = (float*)(smem_raw + OFF_P);   // [row*PR + col]

    const int bh = blockIdx.y;           // 0..31
    const int b  = bh / NHh;
    const int h  = bh % NHh;
    const int q0 = blockIdx.x * 128;

    const int tid = threadIdx.x;
    const int tm  = tid >> 3;            // 0..63
    const int tn  = tid & 7;             // 0..7

    const float* Qb = g_q + (size_t)(b * Ss) * Hh + h * Dd;
    const float* Kb = g_k + (size_t)(b * Ss) * Hh + h * Dd;
    const float* Vb = g_v + (size_t)(b * Ss) * Hh + h * Dd;

    // This thread's two (row, f4) K/V load slots: idx = tid + 512*j
    const int r0 = tid >> 4,            f40 = tid & 15;
    const int r1 = (tid + 512) >> 4,    f41 = tid & 15;   // (tid+512)&15 == tid&15

    // Load Q tile (128 rows x 64 d) into d-pair layout: 2048 f4, 4 per thread
    for (int idx = tid; idx < 128 * 16; idx += 512) {
        int r = idx >> 4, f4 = idx & 15;
        float4 v = *(const float4*)&Qb[(size_t)(q0 + r) * Hh + f4 * 4];
        sQp[(2 * f4 + 0) * QPR + r] = *(ull*)&v.x;
        sQp[(2 * f4 + 1) * QPR + r] = *(ull*)&v.z;
    }

    // Prefetch tile 0 into registers, store into buffer 0
    float4 nk0 = *(const float4*)&Kb[(size_t)r0 * Hh + f40 * 4];
    float4 nk1 = *(const float4*)&Kb[(size_t)r1 * Hh + f41 * 4];
    float4 nv0 = *(const float4*)&Vb[(size_t)r0 * Hh + f40 * 4];
    float4 nv1 = *(const float4*)&Vb[(size_t)r1 * Hh + f41 * 4];
    {
        ull* kb = sKp;  float* vb = sV;
        kb[(2 * f40 + 0) * KPR + r0] = *(ull*)&nk0.x;
        kb[(2 * f40 + 1) * KPR + r0] = *(ull*)&nk0.z;
        kb[(2 * f41 + 0) * KPR + r1] = *(ull*)&nk1.x;
        kb[(2 * f41 + 1) * KPR + r1] = *(ull*)&nk1.z;
        *(float4*)&vb[r0 * VR + f40 * 4] = nv0;
        *(float4*)&vb[r1 * VR + f41 * 4] = nv1;
    }
    __syncthreads();

    float m[2], l[2];
    ull o2[2][4];
#pragma unroll
    for (int i = 0; i < 2; i++) {
        m[i] = -1e30f; l[i] = 0.f;
#pragma unroll
        for (int c = 0; c < 4; c++) o2[i][c] = 0ULL;
    }

    for (int t = 0; t < 32; t++) {
        const int cur = t & 1;
        const ull*   kc = sKp + cur * KTILE;
        const float* vc = sV  + cur * VTILE;

        // Issue next tile's LDGs early (latency hidden behind QK compute)
        if (t < 31) {
            const float* Kn = Kb + (size_t)(t + 1) * 64 * Hh;
            const float* Vn = Vb + (size_t)(t + 1) * 64 * Hh;
            nk0 = *(const float4*)&Kn[(size_t)r0 * Hh + f40 * 4];
            nk1 = *(const float4*)&Kn[(size_t)r1 * Hh + f41 * 4];
            nv0 = *(const float4*)&Vn[(size_t)r0 * Hh + f40 * 4];
            nv1 = *(const float4*)&Vn[(size_t)r1 * Hh + f41 * 4];
        }

        // ---- S = Q K^T  (2 rows x 8 cols per thread) ----
        ull s2[2][8];
#pragma unroll
        for (int i = 0; i < 2; i++)
#pragma unroll
            for (int c = 0; c < 8; c++) s2[i][c] = 0ULL;

#pragma unroll 4
        for (int dp = 0; dp < 32; dp++) {
            ull q2[2], k2[8];
#pragma unroll
            for (int i = 0; i < 2; i++)
                q2[i] = sQp[dp * QPR + tm + 64 * i];
#pragma unroll
            for (int c = 0; c < 8; c++)
                k2[c] = kc[dp * KPR + tn + 8 * c];
#pragma unroll
            for (int i = 0; i < 2; i++)
#pragma unroll
                for (int c = 0; c < 8; c++)
                    s2[i][c] = ffma2(q2[i], k2[c], s2[i][c]);
        }

        // ---- online softmax; write P to smem ----
#pragma unroll
        for (int i = 0; i < 2; i++) {
            float s[8];
            float mrow = -1e30f;
#pragma unroll
            for (int c = 0; c < 8; c++) {
                float lo, hi;
                upk2(s2[i][c], lo, hi);
                s[c] = (lo + hi) * 0.125f;     // 1/sqrt(64)
                mrow = fmaxf(mrow, s[c]);
            }
            mrow = fmaxf(mrow, __shfl_xor_sync(0xffffffffu, mrow, 1));
            mrow = fmaxf(mrow, __shfl_xor_sync(0xffffffffu, mrow, 2));
            mrow = fmaxf(mrow, __shfl_xor_sync(0xffffffffu, mrow, 4));

            float mnew  = fmaxf(m[i], mrow);
            float alpha = __expf(m[i] - mnew);
            float lsum = 0.f;
            int rowbase = (tm + 64 * i) * PR;
#pragma unroll
            for (int c = 0; c < 8; c++) {
                float p = __expf(s[c] - mnew);
                lsum += p;
                sP[rowbase + tn + 8 * c] = p;
            }
            lsum += __shfl_xor_sync(0xffffffffu, lsum, 1);
            lsum += __shfl_xor_sync(0xffffffffu, lsum, 2);
            lsum += __shfl_xor_sync(0xffffffffu, lsum, 4);
            l[i] = l[i] * alpha + lsum;
            m[i] = mnew;
            ull a2 = pk2(alpha, alpha);
#pragma unroll
            for (int c = 0; c < 4; c++) o2[i][c] = fmul2(o2[i][c], a2);
        }
        __syncthreads();   // sP visible (and prev STS already synced)

        // ---- O += P V ----
#pragma unroll 4
        for (int k = 0; k < 64; k++) {
            ull v2[4];
#pragma unroll
            for (int c = 0; c < 4; c++)
                v2[c] = *(const ull*)&vc[k * VR + 2 * tn + 16 * c];
#pragma unroll
            for (int i = 0; i < 2; i++) {
                float p = sP[(tm + 64 * i) * PR + k];
                ull p2 = pk2(p, p);
#pragma unroll
                for (int c = 0; c < 4; c++)
                    o2[i][c] = ffma2(p2, v2[c], o2[i][c]);
            }
        }

        // ---- store prefetched next tile into the other buffer ----
        if (t < 31) {
            ull*   kn = sKp + (cur ^ 1) * KTILE;
            float* vn = sV  + (cur ^ 1) * VTILE;
            kn[(2 * f40 + 0) * KPR + r0] = *(ull*)&nk0.x;
            kn[(2 * f40 + 1) * KPR + r0] = *(ull*)&nk0.z;
            kn[(2 * f41 + 0) * KPR + r1] = *(ull*)&nk1.x;
            kn[(2 * f41 + 1) * KPR + r1] = *(ull*)&nk1.z;
            *(float4*)&vn[r0 * VR + f40 * 4] = nv0;
            *(float4*)&vn[r1 * VR + f41 * 4] = nv1;
            __syncthreads();   // next buffer ready; also gates next sP write
        }
    }

    // Epilogue: normalize and write to concat layout [B*S, H]
#pragma unroll
    for (int i = 0; i < 2; i++) {
        const float inv = 1.f / l[i];
        const int row = q0 + tm + 64 * i;
        float* op = g_ctx + (size_t)(b * Ss + row) * Hh + h * Dd;
#pragma unroll
        for (int c = 0; c < 4; c++) {
            float x, y;
            upk2(o2[i][c], x, y);
            float2 w;
            w.x = x * inv; w.y = y * inv;
            *(float2*)&op[2 * tn + 16 * c] = w;
        }
    }
}

// ---------------------------------------------------------------------------
extern "C" void kernel_launch(void* const* d_in, const int* in_sizes, int n_in,
                              void* d_out, int out_size)
{
    const float* x  = (const float*)d_in[0];
    const float* wq = (const float*)d_in[1];
    const float* bq = (const float*)d_in[2];
    const float* wk = (const float*)d_in[3];
    const float* bk = (const float*)d_in[4];
    const float* wv = (const float*)d_in[5];
    const float* bv = (const float*)d_in[6];
    const float* wo = (const float*)d_in[7];
    const float* bo = (const float*)d_in[8];
    float* out = (float*)d_out;

    cudaFuncSetAttribute(attn_f2, cudaFuncAttributeMaxDynamicSharedMemorySize,
                         SMEM_ATTN);

    dim3 gq(1024 / 128, MROWS / 128, 3);   // (8, 32, 3)
    qkv_f2<<<gq, 256>>>(x, wq, bq, wk, bk, wv, bv);

    dim3 ga(Ss / 128, Bb * NHh);           // (16, 32)
    attn_f2<<<ga, 512, SMEM_ATTN>>>();

    dim3 gg(1024 / 128, MROWS / 128);      // (8, 32)
    oproj_f2<<<gg, 256>>>(wo, bo, out);
}

// round 15
// speedup vs baseline: 1.0974x; 1.0309x over previous
#include <cuda_runtime.h>
#include <cstdint>
#include <math.h>

#define Bb 2
#define Ss 2048
#define Hh 1024
#define NHh 16
#define Dd 64
#define MROWS (Bb * Ss)   // 4096

typedef unsigned long long ull;

// Scratch (no cudaMalloc allowed): Q, K, V, ctx each [4096, 1024] fp32 = 16 MiB
__device__ float g_q[MROWS * Hh];
__device__ float g_k[MROWS * Hh];
__device__ float g_v[MROWS * Hh];
__device__ float g_ctx[MROWS * Hh];

// ===========================================================================
// f32x2 packed-math helpers
// ===========================================================================
__device__ __forceinline__ ull pk2(float x, float y) {
    ull r;
    asm("mov.b64 %0, {%1, %2};" : "=l"(r) : "f"(x), "f"(y));
    return r;
}
__device__ __forceinline__ void upk2(ull v, float& x, float& y) {
    asm("mov.b64 {%0, %1}, %2;" : "=f"(x), "=f"(y) : "l"(v));
}
__device__ __forceinline__ ull ffma2(ull a, ull b, ull c) {
    ull d;
    asm("fma.rn.f32x2 %0, %1, %2, %3;" : "=l"(d) : "l"(a), "l"(b), "l"(c));
    return d;
}
__device__ __forceinline__ ull fmul2(ull a, ull b) {
    ull d;
    asm("mul.rn.f32x2 %0, %1, %2;" : "=l"(d) : "l"(a), "l"(b));
    return d;
}

// ===========================================================================
// GEMM core — 512 threads, 128x128 tile, K-tile 16, 4x8 per thread,
// A stored PRE-DUPLICATED as (a,a) f32x2 pairs in smem (zero packing MOVs
// in the inner loop), double-buffered, 2 CTAs/SM -> 8 warps/SMSP.
// C[m][n] = sum_k A[m][k]*W[n][k] + bias[n].  M=4096, N=1024, K=1024.
// Dynamic smem: As 2*16*132 ull (33792 B) | Bs 2*16*132 float (16896 B).
// ===========================================================================
#define GS_AS_ULL   (2 * 16 * 132)             // ull count
#define GS_BS_OFF   (GS_AS_ULL * 8)            // 33792 bytes
#define SMEM_GEMM   (GS_BS_OFF + 2 * 16 * 132 * 4)   // 50688 bytes

__device__ __forceinline__ void gemm_core(
    const float* __restrict__ A, const float* __restrict__ W,
    const float* __restrict__ bias, float* __restrict__ C,
    char* smem_raw)
{
    ull*   As = (ull*)smem_raw;                 // [buf][kk][m] duplicated pairs
    float* Bs = (float*)(smem_raw + GS_BS_OFF); // [buf][kk][n]

    const int K = 1024, N = 1024;
    const int tid = threadIdx.x;
    const int tx = tid % 16;          // n direction
    const int ty = tid / 16;          // m direction (0..31)
    const int m0 = blockIdx.y * 128;
    const int n0 = blockIdx.x * 128;
    const int lr = tid / 4;           // 0..127
    const int lc = (tid % 4) * 4;     // 0,4,8,12

    ull acc2[4][4];
#pragma unroll
    for (int i = 0; i < 4; i++)
#pragma unroll
        for (int j = 0; j < 4; j++) acc2[i][j] = 0ULL;

    const float* Arow = A + (size_t)(m0 + lr) * K + lc;
    const float* Brow = W + (size_t)(n0 + lr) * K + lc;

    // prefetch + store tile 0
    {
        float4 a = *(const float4*)Arow;
        float4 b = *(const float4*)Brow;
        As[(lc + 0) * 132 + lr] = pk2(a.x, a.x);
        As[(lc + 1) * 132 + lr] = pk2(a.y, a.y);
        As[(lc + 2) * 132 + lr] = pk2(a.z, a.z);
        As[(lc + 3) * 132 + lr] = pk2(a.w, a.w);
        Bs[(lc + 0) * 132 + lr] = b.x;
        Bs[(lc + 1) * 132 + lr] = b.y;
        Bs[(lc + 2) * 132 + lr] = b.z;
        Bs[(lc + 3) * 132 + lr] = b.w;
    }
    __syncthreads();

    for (int t = 0; t < 64; t++) {
        const int cur = t & 1;
        const ull*   ac = As + cur * (16 * 132);
        const float* bc = Bs + cur * (16 * 132);
        float4 na, nb;
        if (t < 63) {
            int k1 = (t + 1) * 16;
            na = *(const float4*)&Arow[k1];
            nb = *(const float4*)&Brow[k1];
        }

#pragma unroll
        for (int kk = 0; kk < 16; kk++) {
            const ull* ap = &ac[kk * 132 + ty * 4];
            ulonglong2 t0 = *(const ulonglong2*)(ap + 0);
            ulonglong2 t1 = *(const ulonglong2*)(ap + 2);
            ull ra2[4] = {t0.x, t0.y, t1.x, t1.y};
            ull rb2[4];
#pragma unroll
            for (int j = 0; j < 4; j++)
                rb2[j] = *(const ull*)&bc[kk * 132 + 2 * tx + 32 * j];
#pragma unroll
            for (int i = 0; i < 4; i++)
#pragma unroll
                for (int j = 0; j < 4; j++)
                    acc2[i][j] = ffma2(ra2[i], rb2[j], acc2[i][j]);
        }

        if (t < 63) {
            ull*   an = As + (cur ^ 1) * (16 * 132);
            float* bn = Bs + (cur ^ 1) * (16 * 132);
            an[(lc + 0) * 132 + lr] = pk2(na.x, na.x);
            an[(lc + 1) * 132 + lr] = pk2(na.y, na.y);
            an[(lc + 2) * 132 + lr] = pk2(na.z, na.z);
            an[(lc + 3) * 132 + lr] = pk2(na.w, na.w);
            bn[(lc + 0) * 132 + lr] = nb.x;
            bn[(lc + 1) * 132 + lr] = nb.y;
            bn[(lc + 2) * 132 + lr] = nb.z;
            bn[(lc + 3) * 132 + lr] = nb.w;
            __syncthreads();
        }
    }

#pragma unroll
    for (int i = 0; i < 4; i++) {
        int row = m0 + ty * 4 + i;
#pragma unroll
        for (int j = 0; j < 4; j++) {
            int col = n0 + 2 * tx + 32 * j;
            float2 bb = *(const float2*)&bias[col];
            float x, y;
            upk2(acc2[i][j], x, y);
            float2 c;
            c.x = x + bb.x;
            c.y = y + bb.y;
            *(float2*)&C[(size_t)row * N + col] = c;
        }
    }
}

// Fused QKV projection: grid.z selects {Q,K,V}
__global__ void __launch_bounds__(512, 2) qkv_f2(
    const float* __restrict__ x,
    const float* __restrict__ wq, const float* __restrict__ bq,
    const float* __restrict__ wk, const float* __restrict__ bk,
    const float* __restrict__ wv, const float* __restrict__ bv)
{
    extern __shared__ char smem_raw[];
    const float* W; const float* bias; float* C;
    if (blockIdx.z == 0)      { W = wq; bias = bq; C = g_q; }
    else if (blockIdx.z == 1) { W = wk; bias = bk; C = g_k; }
    else                      { W = wv; bias = bv; C = g_v; }
    gemm_core(x, W, bias, C, smem_raw);
}

__global__ void __launch_bounds__(512, 2) oproj_f2(
    const float* __restrict__ wo, const float* __restrict__ bo,
    float* __restrict__ out)
{
    extern __shared__ char smem_raw[];
    gemm_core(g_ctx, wo, bo, out, smem_raw);
}

// ===========================================================================
// Flash attention — EXACT R8 version (measured ~920 us = FFMA2-pipe floor).
// Br=128, Bc=64, D=64, 256 threads, 2 CTAs/SM.
// tm=tid/8 (0..31), tn=tid%8. Rows {tm+32i}, i<4. QK cols {tn+8c}, c<8.
// ===========================================================================
#define QPR 129
#define KPR 65
#define VR  68
#define PR  72
#define OFF_QP 0
#define OFF_KP (32 * QPR * 8)                  // 33024
#define OFF_V  (OFF_KP + 32 * KPR * 8)         // 49664
#define OFF_P  (OFF_V + 64 * VR * 4)           // 67072
#define SMEM_ATTN (OFF_P + 128 * PR * 4)       // 103936

__global__ void __launch_bounds__(256, 2) attn_f2()
{
    extern __shared__ char smem_raw[];
    ull*   sQp = (ull*)(smem_raw + OFF_QP);    // [dp*QPR + row], dp=0..31
    ull*   sKp = (ull*)(smem_raw + OFF_KP);    // [dp*KPR + col]
    float* sV  = (float*)(smem_raw + OFF_V);   // [k*VR + d]
    float* sP  = (float*)(smem_raw + OFF_P);   // [row*PR + col]

    const int bh = blockIdx.y;           // 0..31
    const int b  = bh / NHh;
    const int h  = bh % NHh;
    const int q0 = blockIdx.x * 128;

    const int tid = threadIdx.x;
    const int tm  = tid >> 3;            // 0..31
    const int tn  = tid & 7;             // 0..7

    const float* Qb = g_q + (size_t)(b * Ss) * Hh + h * Dd;
    const float* Kb = g_k + (size_t)(b * Ss) * Hh + h * Dd;
    const float* Vb = g_v + (size_t)(b * Ss) * Hh + h * Dd;

    // Load Q tile (128 rows x 64 d) into d-pair layout
    for (int idx = tid; idx < 128 * 16; idx += 256) {
        int r = idx >> 4, f4 = idx & 15;
        float4 v = *(const float4*)&Qb[(size_t)(q0 + r) * Hh + f4 * 4];
        sQp[(2 * f4 + 0) * QPR + r] = *(ull*)&v.x;
        sQp[(2 * f4 + 1) * QPR + r] = *(ull*)&v.z;
    }

    float m[4], l[4];
    ull o2[4][4];
#pragma unroll
    for (int i = 0; i < 4; i++) {
        m[i] = -1e30f; l[i] = 0.f;
#pragma unroll
        for (int c = 0; c < 4; c++) o2[i][c] = 0ULL;
    }

    for (int kt = 0; kt < Ss; kt += 64) {
        __syncthreads();   // prev PV done with sKp/sV/sP; Q stores visible
        for (int idx = tid; idx < 64 * 16; idx += 256) {
            int r = idx >> 4, f4 = idx & 15;
            float4 kv = *(const float4*)&Kb[(size_t)(kt + r) * Hh + f4 * 4];
            sKp[(2 * f4 + 0) * KPR + r] = *(ull*)&kv.x;
            sKp[(2 * f4 + 1) * KPR + r] = *(ull*)&kv.z;
            float4 vv = *(const float4*)&Vb[(size_t)(kt + r) * Hh + f4 * 4];
            *(float4*)&sV[r * VR + f4 * 4] = vv;
        }
        __syncthreads();

        // ---- S = Q K^T  (4 rows x 8 cols per thread) ----
        ull s2[4][8];
#pragma unroll
        for (int i = 0; i < 4; i++)
#pragma unroll
            for (int c = 0; c < 8; c++) s2[i][c] = 0ULL;

#pragma unroll 4
        for (int dp = 0; dp < 32; dp++) {
            ull q2[4], k2[8];
#pragma unroll
            for (int i = 0; i < 4; i++)
                q2[i] = sQp[dp * QPR + tm + 32 * i];
#pragma unroll
            for (int c = 0; c < 8; c++)
                k2[c] = sKp[dp * KPR + tn + 8 * c];
#pragma unroll
            for (int i = 0; i < 4; i++)
#pragma unroll
                for (int c = 0; c < 8; c++)
                    s2[i][c] = ffma2(q2[i], k2[c], s2[i][c]);
        }

        // ---- online softmax (per row; reduce across 8 tn lanes) ----
#pragma unroll
        for (int i = 0; i < 4; i++) {
            float s[8];
            float mrow = -1e30f;
#pragma unroll
            for (int c = 0; c < 8; c++) {
                float lo, hi;
                upk2(s2[i][c], lo, hi);
                s[c] = (lo + hi) * 0.125f;     // 1/sqrt(64)
                mrow = fmaxf(mrow, s[c]);
            }
            mrow = fmaxf(mrow, __shfl_xor_sync(0xffffffffu, mrow, 1));
            mrow = fmaxf(mrow, __shfl_xor_sync(0xffffffffu, mrow, 2));
            mrow = fmaxf(mrow, __shfl_xor_sync(0xffffffffu, mrow, 4));

            float mnew  = fmaxf(m[i], mrow);
            float alpha = __expf(m[i] - mnew);
            float lsum = 0.f;
            int rowbase = (tm + 32 * i) * PR;
#pragma unroll
            for (int c = 0; c < 8; c++) {
                float p = __expf(s[c] - mnew);
                lsum += p;
                sP[rowbase + tn + 8 * c] = p;
            }
            lsum += __shfl_xor_sync(0xffffffffu, lsum, 1);
            lsum += __shfl_xor_sync(0xffffffffu, lsum, 2);
            lsum += __shfl_xor_sync(0xffffffffu, lsum, 4);
            l[i] = l[i] * alpha + lsum;
            m[i] = mnew;
            ull a2 = pk2(alpha, alpha);
#pragma unroll
            for (int c = 0; c < 4; c++) o2[i][c] = fmul2(o2[i][c], a2);
        }
        __syncthreads();   // sP fully written

        // ---- O += P V  (4 rows x 4 d-pairs per thread) ----
#pragma unroll 4
        for (int k = 0; k < 64; k++) {
            ull v2[4];
#pragma unroll
            for (int c = 0; c < 4; c++)
                v2[c] = *(const ull*)&sV[k * VR + 2 * tn + 16 * c];
#pragma unroll
            for (int i = 0; i < 4; i++) {
                float p = sP[(tm + 32 * i) * PR + k];
                ull p2 = pk2(p, p);
#pragma unroll
                for (int c = 0; c < 4; c++)
                    o2[i][c] = ffma2(p2, v2[c], o2[i][c]);
            }
        }
    }

    // Epilogue: normalize and write to concat layout [B*S, H]
#pragma unroll
    for (int i = 0; i < 4; i++) {
        const float inv = 1.f / l[i];
        const int row = q0 + tm + 32 * i;
        float* op = g_ctx + (size_t)(b * Ss + row) * Hh + h * Dd;
#pragma unroll
        for (int c = 0; c < 4; c++) {
            float x, y;
            upk2(o2[i][c], x, y);
            float2 w;
            w.x = x * inv; w.y = y * inv;
            *(float2*)&op[2 * tn + 16 * c] = w;
        }
    }
}

// ---------------------------------------------------------------------------
extern "C" void kernel_launch(void* const* d_in, const int* in_sizes, int n_in,
                              void* d_out, int out_size)
{
    const float* x  = (const float*)d_in[0];
    const float* wq = (const float*)d_in[1];
    const float* bq = (const float*)d_in[2];
    const float* wk = (const float*)d_in[3];
    const float* bk = (const float*)d_in[4];
    const float* wv = (const float*)d_in[5];
    const float* bv = (const float*)d_in[6];
    const float* wo = (const float*)d_in[7];
    const float* bo = (const float*)d_in[8];
    float* out = (float*)d_out;

    cudaFuncSetAttribute(attn_f2, cudaFuncAttributeMaxDynamicSharedMemorySize,
                         SMEM_ATTN);
    cudaFuncSetAttribute(qkv_f2, cudaFuncAttributeMaxDynamicSharedMemorySize,
                         SMEM_GEMM);
    cudaFuncSetAttribute(oproj_f2, cudaFuncAttributeMaxDynamicSharedMemorySize,
                         SMEM_GEMM);

    dim3 gq(1024 / 128, MROWS / 128, 3);   // (8, 32, 3)
    qkv_f2<<<gq, 512, SMEM_GEMM>>>(x, wq, bq, wk, bk, wv, bv);

    dim3 ga(Ss / 128, Bb * NHh);           // (16, 32)
    attn_f2<<<ga, 256, SMEM_ATTN>>>();

    dim3 gg(1024 / 128, MROWS / 128);      // (8, 32)
    oproj_f2<<<gg, 512, SMEM_GEMM>>>(wo, bo, out);
}

// round 16
// speedup vs baseline: 1.3369x; 1.2183x over previous
#include <cuda_runtime.h>
#include <cstdint>
#include <math.h>

#define Bb 2
#define Ss 2048
#define Hh 1024
#define NHh 16
#define Dd 64
#define MROWS (Bb * Ss)   // 4096

typedef unsigned long long ull;

// Scratch (no cudaMalloc allowed): Q, K, V, ctx each [4096, 1024] fp32 = 16 MiB
__device__ float g_q[MROWS * Hh];
__device__ float g_k[MROWS * Hh];
__device__ float g_v[MROWS * Hh];
__device__ float g_ctx[MROWS * Hh];

// ===========================================================================
// f32x2 packed-math helpers
// ===========================================================================
__device__ __forceinline__ ull pk2(float x, float y) {
    ull r;
    asm("mov.b64 %0, {%1, %2};" : "=l"(r) : "f"(x), "f"(y));
    return r;
}
__device__ __forceinline__ void upk2(ull v, float& x, float& y) {
    asm("mov.b64 {%0, %1}, %2;" : "=f"(x), "=f"(y) : "l"(v));
}
__device__ __forceinline__ ull ffma2(ull a, ull b, ull c) {
    ull d;
    asm("fma.rn.f32x2 %0, %1, %2, %3;" : "=l"(d) : "l"(a), "l"(b), "l"(c));
    return d;
}
__device__ __forceinline__ ull fmul2(ull a, ull b) {
    ull d;
    asm("mul.rn.f32x2 %0, %1, %2;" : "=l"(d) : "l"(a), "l"(b));
    return d;
}

// ===========================================================================
// GEMM core — EXACT R8 version (256 thr, 8x8/thread, ~37% crossbar, regs~128
// -> 2 CTAs/SM).  C[m][n] = sum_k A[m][k]*W[n][k] + bias[n].
// ===========================================================================
__device__ __forceinline__ void gemm_core(
    const float* __restrict__ A, const float* __restrict__ W,
    const float* __restrict__ bias, float* __restrict__ C,
    float (*As)[16][132], float (*Bs)[16][132])
{
    const int K = 1024, N = 1024;
    const int tid = threadIdx.x;
    const int tx = tid % 16;          // n direction
    const int ty = tid / 16;          // m direction
    const int m0 = blockIdx.y * 128;
    const int n0 = blockIdx.x * 128;
    const int lr = tid / 4;           // 0..63
    const int lc = (tid % 4) * 4;     // 0,4,8,12

    ull acc2[8][4];
#pragma unroll
    for (int i = 0; i < 8; i++)
#pragma unroll
        for (int j = 0; j < 4; j++) acc2[i][j] = 0ULL;

    const float* Arow0 = A + (size_t)(m0 + lr) * K + lc;
    const float* Arow1 = A + (size_t)(m0 + lr + 64) * K + lc;
    const float* Brow0 = W + (size_t)(n0 + lr) * K + lc;
    const float* Brow1 = W + (size_t)(n0 + lr + 64) * K + lc;

    {
        float4 a0 = *(const float4*)Arow0;
        float4 a1 = *(const float4*)Arow1;
        float4 b0 = *(const float4*)Brow0;
        float4 b1 = *(const float4*)Brow1;
        As[0][lc + 0][lr] = a0.x; As[0][lc + 1][lr] = a0.y;
        As[0][lc + 2][lr] = a0.z; As[0][lc + 3][lr] = a0.w;
        As[0][lc + 0][lr + 64] = a1.x; As[0][lc + 1][lr + 64] = a1.y;
        As[0][lc + 2][lr + 64] = a1.z; As[0][lc + 3][lr + 64] = a1.w;
        Bs[0][lc + 0][lr] = b0.x; Bs[0][lc + 1][lr] = b0.y;
        Bs[0][lc + 2][lr] = b0.z; Bs[0][lc + 3][lr] = b0.w;
        Bs[0][lc + 0][lr + 64] = b1.x; Bs[0][lc + 1][lr + 64] = b1.y;
        Bs[0][lc + 2][lr + 64] = b1.z; Bs[0][lc + 3][lr + 64] = b1.w;
    }
    __syncthreads();

    for (int t = 0; t < 64; t++) {
        const int cur = t & 1;
        float4 na0, na1, nb0, nb1;
        if (t < 63) {
            int k1 = (t + 1) * 16;
            na0 = *(const float4*)&Arow0[k1];
            na1 = *(const float4*)&Arow1[k1];
            nb0 = *(const float4*)&Brow0[k1];
            nb1 = *(const float4*)&Brow1[k1];
        }

#pragma unroll
        for (int kk = 0; kk < 16; kk++) {
            float4 a0 = *(const float4*)&As[cur][kk][ty * 8];
            float4 a1 = *(const float4*)&As[cur][kk][ty * 8 + 4];
            ull ra2[8];
            ra2[0] = pk2(a0.x, a0.x); ra2[1] = pk2(a0.y, a0.y);
            ra2[2] = pk2(a0.z, a0.z); ra2[3] = pk2(a0.w, a0.w);
            ra2[4] = pk2(a1.x, a1.x); ra2[5] = pk2(a1.y, a1.y);
            ra2[6] = pk2(a1.z, a1.z); ra2[7] = pk2(a1.w, a1.w);
            ull rb2[4];
#pragma unroll
            for (int j = 0; j < 4; j++)
                rb2[j] = *(const ull*)&Bs[cur][kk][2 * tx + 32 * j];
#pragma unroll
            for (int i = 0; i < 8; i++)
#pragma unroll
                for (int j = 0; j < 4; j++)
                    acc2[i][j] = ffma2(ra2[i], rb2[j], acc2[i][j]);
        }

        if (t < 63) {
            const int nb = cur ^ 1;
            As[nb][lc + 0][lr] = na0.x; As[nb][lc + 1][lr] = na0.y;
            As[nb][lc + 2][lr] = na0.z; As[nb][lc + 3][lr] = na0.w;
            As[nb][lc + 0][lr + 64] = na1.x; As[nb][lc + 1][lr + 64] = na1.y;
            As[nb][lc + 2][lr + 64] = na1.z; As[nb][lc + 3][lr + 64] = na1.w;
            Bs[nb][lc + 0][lr] = nb0.x; Bs[nb][lc + 1][lr] = nb0.y;
            Bs[nb][lc + 2][lr] = nb0.z; Bs[nb][lc + 3][lr] = nb0.w;
            Bs[nb][lc + 0][lr + 64] = nb1.x; Bs[nb][lc + 1][lr + 64] = nb1.y;
            Bs[nb][lc + 2][lr + 64] = nb1.z; Bs[nb][lc + 3][lr + 64] = nb1.w;
            __syncthreads();
        }
    }

#pragma unroll
    for (int i = 0; i < 8; i++) {
        int row = m0 + ty * 8 + i;
#pragma unroll
        for (int j = 0; j < 4; j++) {
            int col = n0 + 2 * tx + 32 * j;
            float2 bb = *(const float2*)&bias[col];
            float x, y;
            upk2(acc2[i][j], x, y);
            float2 c;
            c.x = x + bb.x;
            c.y = y + bb.y;
            *(float2*)&C[(size_t)row * N + col] = c;
        }
    }
}

// Fused QKV projection: grid.z selects {Q,K,V}
__global__ void __launch_bounds__(256, 2) qkv_f2(
    const float* __restrict__ x,
    const float* __restrict__ wq, const float* __restrict__ bq,
    const float* __restrict__ wk, const float* __restrict__ bk,
    const float* __restrict__ wv, const float* __restrict__ bv)
{
    __shared__ float As[2][16][132];
    __shared__ float Bs[2][16][132];
    const float* W; const float* bias; float* C;
    if (blockIdx.z == 0)      { W = wq; bias = bq; C = g_q; }
    else if (blockIdx.z == 1) { W = wk; bias = bk; C = g_k; }
    else                      { W = wv; bias = bv; C = g_v; }
    gemm_core(x, W, bias, C, As, Bs);
}

__global__ void __launch_bounds__(256, 2) oproj_f2(
    const float* __restrict__ wo, const float* __restrict__ bo,
    float* __restrict__ out)
{
    __shared__ float As[2][16][132];
    __shared__ float Bs[2][16][132];
    gemm_core(g_ctx, wo, bo, out, As, Bs);
}

// ===========================================================================
// Flash attention: Br=128, Bc=64, D=64, 256 threads, 2 CTAs/SM.
// Wavefront-reduced layouts vs R8:
//  - Q ROW-major d-pairs, stride QS=34 ull -> LDS128 loads q for 2 dp at once
//  - P transposed [col][tm*4+i] float4   -> 1 LDS128/k in PV, 8 STS128 total
// K ([dp][col], KPR=65) and V ([k][d], VR=68) unchanged from R8.
// tm=tid/8 (0..31), tn=tid%8. Rows {tm+32i}, i<4. QK cols {tn+8c}, c<8.
// ===========================================================================
#define QS  34
#define KPR 65
#define VR  68
#define PS  132
#define OFF_Q  0
#define OFF_K  (128 * QS * 8)                  // 34816
#define OFF_V  (OFF_K + 32 * KPR * 8)          // 51456
#define OFF_P  (OFF_V + 64 * VR * 4)           // 68864
#define SMEM_ATTN (OFF_P + 64 * PS * 4)        // 102656

__global__ void __launch_bounds__(256, 2) attn_f2()
{
    extern __shared__ char smem_raw[];
    ull*   sQ  = (ull*)(smem_raw + OFF_Q);     // [row*QS + dp]
    ull*   sKp = (ull*)(smem_raw + OFF_K);     // [dp*KPR + col]
    float* sV  = (float*)(smem_raw + OFF_V);   // [k*VR + d]
    float* sP  = (float*)(smem_raw + OFF_P);   // [k*PS + tm*4 + i]

    const int bh = blockIdx.y;           // 0..31
    const int b  = bh / NHh;
    const int h  = bh % NHh;
    const int q0 = blockIdx.x * 128;

    const int tid = threadIdx.x;
    const int tm  = tid >> 3;            // 0..31
    const int tn  = tid & 7;             // 0..7

    const float* Qb = g_q + (size_t)(b * Ss) * Hh + h * Dd;
    const float* Kb = g_k + (size_t)(b * Ss) * Hh + h * Dd;
    const float* Vb = g_v + (size_t)(b * Ss) * Hh + h * Dd;

    // Load Q tile (128 rows x 64 d) into ROW-major d-pair layout
    for (int idx = tid; idx < 128 * 16; idx += 256) {
        int r = idx >> 4, f4 = idx & 15;
        float4 v = *(const float4*)&Qb[(size_t)(q0 + r) * Hh + f4 * 4];
        sQ[r * QS + 2 * f4 + 0] = *(ull*)&v.x;
        sQ[r * QS + 2 * f4 + 1] = *(ull*)&v.z;
    }

    float m[4], l[4];
    ull o2[4][4];
#pragma unroll
    for (int i = 0; i < 4; i++) {
        m[i] = -1e30f; l[i] = 0.f;
#pragma unroll
        for (int c = 0; c < 4; c++) o2[i][c] = 0ULL;
    }

    for (int kt = 0; kt < Ss; kt += 64) {
        __syncthreads();   // prev PV done with sKp/sV/sP; Q stores visible
        for (int idx = tid; idx < 64 * 16; idx += 256) {
            int r = idx >> 4, f4 = idx & 15;
            float4 kv = *(const float4*)&Kb[(size_t)(kt + r) * Hh + f4 * 4];
            sKp[(2 * f4 + 0) * KPR + r] = *(ull*)&kv.x;
            sKp[(2 * f4 + 1) * KPR + r] = *(ull*)&kv.z;
            float4 vv = *(const float4*)&Vb[(size_t)(kt + r) * Hh + f4 * 4];
            *(float4*)&sV[r * VR + f4 * 4] = vv;
        }
        __syncthreads();

        // ---- S = Q K^T  (4 rows x 8 cols per thread, 2 dp per step) ----
        ull s2[4][8];
#pragma unroll
        for (int i = 0; i < 4; i++)
#pragma unroll
            for (int c = 0; c < 8; c++) s2[i][c] = 0ULL;

#pragma unroll 4
        for (int dp = 0; dp < 32; dp += 2) {
            ulonglong2 q01[4];
#pragma unroll
            for (int i = 0; i < 4; i++)
                q01[i] = *(const ulonglong2*)&sQ[(tm + 32 * i) * QS + dp];
            ull k2a[8], k2b[8];
#pragma unroll
            for (int c = 0; c < 8; c++) {
                k2a[c] = sKp[(dp + 0) * KPR + tn + 8 * c];
                k2b[c] = sKp[(dp + 1) * KPR + tn + 8 * c];
            }
#pragma unroll
            for (int i = 0; i < 4; i++)
#pragma unroll
                for (int c = 0; c < 8; c++) {
                    s2[i][c] = ffma2(q01[i].x, k2a[c], s2[i][c]);
                    s2[i][c] = ffma2(q01[i].y, k2b[c], s2[i][c]);
                }
        }

        // ---- online softmax (per row; reduce across 8 tn lanes) ----
        float p[4][8];
#pragma unroll
        for (int i = 0; i < 4; i++) {
            float s[8];
            float mrow = -1e30f;
#pragma unroll
            for (int c = 0; c < 8; c++) {
                float lo, hi;
                upk2(s2[i][c], lo, hi);
                s[c] = (lo + hi) * 0.125f;     // 1/sqrt(64)
                mrow = fmaxf(mrow, s[c]);
            }
            mrow = fmaxf(mrow, __shfl_xor_sync(0xffffffffu, mrow, 1));
            mrow = fmaxf(mrow, __shfl_xor_sync(0xffffffffu, mrow, 2));
            mrow = fmaxf(mrow, __shfl_xor_sync(0xffffffffu, mrow, 4));

            float mnew  = fmaxf(m[i], mrow);
            float alpha = __expf(m[i] - mnew);
            float lsum = 0.f;
#pragma unroll
            for (int c = 0; c < 8; c++) {
                p[i][c] = __expf(s[c] - mnew);
                lsum += p[i][c];
            }
            lsum += __shfl_xor_sync(0xffffffffu, lsum, 1);
            lsum += __shfl_xor_sync(0xffffffffu, lsum, 2);
            lsum += __shfl_xor_sync(0xffffffffu, lsum, 4);
            l[i] = l[i] * alpha + lsum;
            m[i] = mnew;
            ull a2 = pk2(alpha, alpha);
#pragma unroll
            for (int c = 0; c < 4; c++) o2[i][c] = fmul2(o2[i][c], a2);
        }

        // ---- store P transposed: one float4 (4 rows) per column ----
#pragma unroll
        for (int c = 0; c < 8; c++) {
            float4 pf;
            pf.x = p[0][c]; pf.y = p[1][c]; pf.z = p[2][c]; pf.w = p[3][c];
            *(float4*)&sP[(tn + 8 * c) * PS + tm * 4] = pf;
        }
        __syncthreads();   // sP fully written

        // ---- O += P V  (1 LDS128 for 4 rows' p, 4 LDS64 for v, per k) ----
#pragma unroll 4
        for (int k = 0; k < 64; k++) {
            float4 pf = *(const float4*)&sP[k * PS + tm * 4];
            ull v2[4];
#pragma unroll
            for (int c = 0; c < 4; c++)
                v2[c] = *(const ull*)&sV[k * VR + 2 * tn + 16 * c];
            ull p2;
            p2 = pk2(pf.x, pf.x);
#pragma unroll
            for (int c = 0; c < 4; c++) o2[0][c] = ffma2(p2, v2[c], o2[0][c]);
            p2 = pk2(pf.y, pf.y);
#pragma unroll
            for (int c = 0; c < 4; c++) o2[1][c] = ffma2(p2, v2[c], o2[1][c]);
            p2 = pk2(pf.z, pf.z);
#pragma unroll
            for (int c = 0; c < 4; c++) o2[2][c] = ffma2(p2, v2[c], o2[2][c]);
            p2 = pk2(pf.w, pf.w);
#pragma unroll
            for (int c = 0; c < 4; c++) o2[3][c] = ffma2(p2, v2[c], o2[3][c]);
        }
    }

    // Epilogue: normalize and write to concat layout [B*S, H]
#pragma unroll
    for (int i = 0; i < 4; i++) {
        const float inv = 1.f / l[i];
        const int row = q0 + tm + 32 * i;
        float* op = g_ctx + (size_t)(b * Ss + row) * Hh + h * Dd;
#pragma unroll
        for (int c = 0; c < 4; c++) {
            float x, y;
            upk2(o2[i][c], x, y);
            float2 w;
            w.x = x * inv; w.y = y * inv;
            *(float2*)&op[2 * tn + 16 * c] = w;
        }
    }
}

// ---------------------------------------------------------------------------
extern "C" void kernel_launch(void* const* d_in, const int* in_sizes, int n_in,
                              void* d_out, int out_size)
{
    const float* x  = (const float*)d_in[0];
    const float* wq = (const float*)d_in[1];
    const float* bq = (const float*)d_in[2];
    const float* wk = (const float*)d_in[3];
    const float* bk = (const float*)d_in[4];
    const float* wv = (const float*)d_in[5];
    const float* bv = (const float*)d_in[6];
    const float* wo = (const float*)d_in[7];
    const float* bo = (const float*)d_in[8];
    float* out = (float*)d_out;

    cudaFuncSetAttribute(attn_f2, cudaFuncAttributeMaxDynamicSharedMemorySize,
                         SMEM_ATTN);

    dim3 gq(1024 / 128, MROWS / 128, 3);   // (8, 32, 3)
    qkv_f2<<<gq, 256>>>(x, wq, bq, wk, bk, wv, bv);

    dim3 ga(Ss / 128, Bb * NHh);           // (16, 32)
    attn_f2<<<ga, 256, SMEM_ATTN>>>();

    dim3 gg(1024 / 128, MROWS / 128);      // (8, 32)
    oproj_f2<<<gg, 256>>>(wo, bo, out);
}